// round 3
// baseline (speedup 1.0000x reference)
#include <cuda_runtime.h>
#include <cstdint>

#define N_TOK 32768
#define DIM 768
#define NE 64
#define NH 256
#define NH2 128
#define NO 2

// ---------------- scratch (no allocations allowed) ----------------
__device__ float g_mu[N_TOK];
__device__ float g_rstd[N_TOK];
__device__ int g_hist[NE];
__device__ int g_off[NE + 1];
__device__ int g_cur[NE];
__device__ int g_tokidx[N_TOK];
__device__ int g_ntiles;
__device__ int g_p64;  // 1 if properties buffer is int64, 0 if int32
#define MAXT 512
__device__ int g_tile_head[MAXT];
__device__ int g_tile_start[MAXT];
__device__ int g_tile_rows[MAXT];

// ---------------- tf32 helpers ----------------
__device__ __forceinline__ uint32_t f2tf(float x) {
    uint32_t r;
    asm("cvt.rna.tf32.f32 %0, %1;" : "=r"(r) : "f"(x));
    return r;
}

__device__ __forceinline__ void mma_tf32(float* d, const uint32_t* a, const uint32_t* b) {
    asm volatile(
        "mma.sync.aligned.m16n8k8.row.col.f32.tf32.tf32.f32 "
        "{%0,%1,%2,%3}, {%4,%5,%6,%7}, {%8,%9}, {%0,%1,%2,%3};\n"
        : "+f"(d[0]), "+f"(d[1]), "+f"(d[2]), "+f"(d[3])
        : "r"(a[0]), "r"(a[1]), "r"(a[2]), "r"(a[3]), "r"(b[0]), "r"(b[1]));
}

// property read that works for both int32 and int64 buffers, always in [0,63]
__device__ __forceinline__ int get_prop(const void* props, int t, int p64) {
    int v;
    if (p64) v = (int)((const long long*)props)[t];
    else     v = ((const int*)props)[t];
    return v & (NE - 1);
}

// ---------------- kernel 0: reset + dtype detection ----------------
__global__ void k_reset(const unsigned* __restrict__ pw) {
    if (threadIdx.x < NE) g_hist[threadIdx.x] = 0;
    // Detect int64 vs int32: if properties is int64 with values in [0,64),
    // every odd 32-bit word (the high half) is zero. For int32 data these
    // words are random head indices — all-zero over 128 samples is impossible.
    if (threadIdx.x < 32) {
        int odd_nonzero = 0;
#pragma unroll
        for (int i = 0; i < 4; i++) {
            if (pw[2 * (threadIdx.x + 32 * i) + 1] != 0u) odd_nonzero = 1;
        }
        unsigned b = __ballot_sync(0xFFFFFFFFu, odd_nonzero);
        if (threadIdx.x == 0) g_p64 = (b == 0u) ? 1 : 0;
    }
}

// ---------------- kernel 1: LN stats + histogram + masked-output zero ----------------
__global__ void k_stats(const float* __restrict__ hidden,
                        const void* __restrict__ props,
                        const float* __restrict__ mask,
                        float* __restrict__ out) {
    int token = blockIdx.x * 8 + (threadIdx.x >> 5);
    int lane = threadIdx.x & 31;
    const float* xr = hidden + (size_t)token * DIM;
    float s = 0.f, q = 0.f;
#pragma unroll
    for (int i = 0; i < DIM / 32; i++) {
        float v = xr[lane + 32 * i];
        s += v; q += v * v;
    }
#pragma unroll
    for (int o = 16; o > 0; o >>= 1) {
        s += __shfl_xor_sync(0xFFFFFFFFu, s, o);
        q += __shfl_xor_sync(0xFFFFFFFFu, q, o);
    }
    if (lane == 0) {
        float mu = s * (1.f / DIM);
        float var = q * (1.f / DIM) - mu * mu;
        g_mu[token] = mu;
        g_rstd[token] = rsqrtf(var + 1e-5f);
        float m = mask[token];
        if (m > 0.f) {
            atomicAdd(&g_hist[get_prop(props, token, g_p64)], 1);
        } else {
            out[token * 2 + 0] = 0.f;
            out[token * 2 + 1] = 0.f;
        }
    }
}

// ---------------- kernel 2: scan + tile plan (single block) ----------------
__global__ void k_plan() {
    if (threadIdx.x == 0) {
        int off = 0, nt = 0;
        for (int e = 0; e < NE; e++) {
            g_off[e] = off;
            int c = g_hist[e];
            for (int s = 0; s < c && nt < MAXT; s += 128) {
                g_tile_head[nt] = e;
                g_tile_start[nt] = off + s;
                g_tile_rows[nt] = min(128, c - s);
                nt++;
            }
            g_cur[e] = 0;
            off += c;
        }
        g_off[NE] = off;
        g_ntiles = nt;
    }
}

// ---------------- kernel 3: scatter token ids into head segments ----------------
__global__ void k_scatter(const void* __restrict__ props,
                          const float* __restrict__ mask) {
    int t = blockIdx.x * 256 + threadIdx.x;
    if (mask[t] > 0.f) {
        int p = get_prop(props, t, g_p64);
        int pos = atomicAdd(&g_cur[p], 1);
        int dst = g_off[p] + pos;
        if (dst < N_TOK) g_tokidx[dst] = t;
    }
}

// ---------------- kernel 4: fused grouped adapter ----------------
#define LDA 36    // 128 x 36 fp32  (gathered/LN'd A chunk, tf32 bits) — conflict-free frag LDS
#define LDW 264   // 32 x 264       (W1 chunk)
#define LDW2 136  // 32 x 136       (W2 chunk, inside sW buffer)
#define LDH 264   // 128 x 264      (H1)
#define LDH2 132  // 128 x 132      (H2, overlaps H1 region)

#define SMEM_FLOATS (128 * LDA + 32 * LDW + 128 * LDH + 128)
#define SMEM_BYTES (SMEM_FLOATS * 4)

__global__ __launch_bounds__(512) void k_main(
    const float* __restrict__ hidden, const float* __restrict__ base,
    const float* __restrict__ ln_g, const float* __restrict__ ln_b,
    const float* __restrict__ W1, const float* __restrict__ b1,
    const float* __restrict__ W2, const float* __restrict__ b2,
    const float* __restrict__ W3, const float* __restrict__ b3,
    float* __restrict__ out)
{
    if ((int)blockIdx.x >= g_ntiles) return;

    extern __shared__ float sm[];
    float* sA = sm;                       // 128*36 = 4608 floats
    float* sW = sA + 128 * LDA;           // 32*264 = 8448 floats
    float* sH1 = sW + 32 * LDW;           // 128*264 = 33792 floats
    int* sTok = (int*)(sH1 + 128 * LDH);  // 128 ints
    float* sH2 = sH1;                     // [128][LDH2], reuses H1 region after GEMM2
    float* sW3 = sA;                      // 256 floats, reuses A region after GEMM1

    const int tid = threadIdx.x;
    const int wid = tid >> 5;
    const int lane = tid & 31;
    const int g = lane >> 2;   // groupID 0..7
    const int t4 = lane & 3;   // threadID in group 0..3
    const int e = g_tile_head[blockIdx.x] & (NE - 1);
    const int seg = g_tile_start[blockIdx.x];
    const int rows = g_tile_rows[blockIdx.x];

    if (tid < 128) {
        int tok = -1;
        if (tid < rows) {
            tok = g_tokidx[seg + tid];
            if (tok < 0 || tok >= N_TOK) tok = -1;
        }
        sTok[tid] = tok;
    }
    __syncthreads();

    // per-thread gather assignment: 4 threads per row, 8 cols each
    const int arow = tid >> 2;
    const int acol = (tid & 3) * 8;
    const int tokr = sTok[arow];
    float mu = 0.f, rs = 0.f;
    const float* xrow = hidden;
    if (tokr >= 0) {
        mu = g_mu[tokr];
        rs = g_rstd[tokr];
        xrow = hidden + (size_t)tokr * DIM;
    }

    const uint32_t* sAu = (const uint32_t*)sA;
    const uint32_t* sWu = (const uint32_t*)sW;
    const uint32_t* sH1u = (const uint32_t*)sH1;

    // ===================== GEMM1: [128,768] x [768,256] =====================
    // warp tile: 32 (m) x 64 (n); m16n8k8 => 2 m-tiles x 8 n-tiles
    const int wm = wid >> 2;  // 0..3 (rows of 32)
    const int wn = wid & 3;   // 0..3 (cols of 64)
    float acc1[2][8][4];
#pragma unroll
    for (int i = 0; i < 2; i++)
#pragma unroll
        for (int j = 0; j < 8; j++)
#pragma unroll
            for (int q = 0; q < 4; q++) acc1[i][j][q] = 0.f;

    for (int k0 = 0; k0 < DIM; k0 += 32) {
        // gather + LN-affine A chunk -> sA (tf32 bits stored as float bits)
        {
            float* d = &sA[arow * LDA + acol];
            if (tokr >= 0) {
                const float* xp = xrow + k0 + acol;
                const float* gp = ln_g + (size_t)e * DIM + k0 + acol;
                const float* bp = ln_b + (size_t)e * DIM + k0 + acol;
                float4 x0 = *(const float4*)(xp);
                float4 x1 = *(const float4*)(xp + 4);
                float4 g0 = *(const float4*)(gp);
                float4 g1 = *(const float4*)(gp + 4);
                float4 c0 = *(const float4*)(bp);
                float4 c1 = *(const float4*)(bp + 4);
                uint32_t* du = (uint32_t*)d;
                du[0] = f2tf((x0.x - mu) * rs * g0.x + c0.x);
                du[1] = f2tf((x0.y - mu) * rs * g0.y + c0.y);
                du[2] = f2tf((x0.z - mu) * rs * g0.z + c0.z);
                du[3] = f2tf((x0.w - mu) * rs * g0.w + c0.w);
                du[4] = f2tf((x1.x - mu) * rs * g1.x + c1.x);
                du[5] = f2tf((x1.y - mu) * rs * g1.y + c1.y);
                du[6] = f2tf((x1.z - mu) * rs * g1.z + c1.z);
                du[7] = f2tf((x1.w - mu) * rs * g1.w + c1.w);
            } else {
#pragma unroll
                for (int j = 0; j < 8; j++) d[j] = 0.f;
            }
        }
        // W1 chunk [32,256] -> sW
        {
            const float4* wsrc = (const float4*)(W1 + ((size_t)e * DIM + k0) * NH);
#pragma unroll
            for (int i = 0; i < 4; i++) {
                int idx = tid + 512 * i;  // < 2048
                float4 f = wsrc[idx];
                int r = idx >> 6;         // 64 float4 per row
                int c = (idx & 63) * 4;
                uint32_t* d = (uint32_t*)&sW[r * LDW + c];
                d[0] = f2tf(f.x);
                d[1] = f2tf(f.y);
                d[2] = f2tf(f.z);
                d[3] = f2tf(f.w);
            }
        }
        __syncthreads();
#pragma unroll
        for (int kk = 0; kk < 32; kk += 8) {
            uint32_t afr[2][4];
#pragma unroll
            for (int i = 0; i < 2; i++) {
                int r0 = wm * 32 + i * 16;
                afr[i][0] = sAu[(r0 + g) * LDA + kk + t4];
                afr[i][1] = sAu[(r0 + g + 8) * LDA + kk + t4];
                afr[i][2] = sAu[(r0 + g) * LDA + kk + t4 + 4];
                afr[i][3] = sAu[(r0 + g + 8) * LDA + kk + t4 + 4];
            }
#pragma unroll
            for (int j = 0; j < 8; j++) {
                uint32_t bfr[2];
                int c = wn * 64 + j * 8 + g;
                bfr[0] = sWu[(kk + t4) * LDW + c];
                bfr[1] = sWu[(kk + t4 + 4) * LDW + c];
                mma_tf32(acc1[0][j], afr[0], bfr);
                mma_tf32(acc1[1][j], afr[1], bfr);
            }
        }
        __syncthreads();
    }
    // store acc1 -> sH1 (D layout: c0/c1 at (row, 2*t4), c2/c3 at (row+8, 2*t4))
#pragma unroll
    for (int i = 0; i < 2; i++) {
        int r0 = wm * 32 + i * 16 + g;
#pragma unroll
        for (int j = 0; j < 8; j++) {
            int c = wn * 64 + j * 8 + 2 * t4;
            *(float2*)&sH1[r0 * LDH + c] = make_float2(acc1[i][j][0], acc1[i][j][1]);
            *(float2*)&sH1[(r0 + 8) * LDH + c] = make_float2(acc1[i][j][2], acc1[i][j][3]);
        }
    }
    __syncthreads();
    // bias + ReLU + tf32-quantize H1
    for (int i = tid; i < 128 * NH; i += 512) {
        int r = i >> 8, c = i & 255;
        float v = sH1[r * LDH + c] + b1[(size_t)e * NH + c];
        ((uint32_t*)sH1)[r * LDH + c] = f2tf(fmaxf(v, 0.f));
    }
    __syncthreads();

    // ===================== GEMM2: [128,256] x [256,128] =====================
    // warp tile: 32 (m) x 32 (n); 2 m-tiles x 4 n-tiles
    const int wm2 = wid >> 2;
    const int wn2 = wid & 3;
    float acc2[2][4][4];
#pragma unroll
    for (int i = 0; i < 2; i++)
#pragma unroll
        for (int j = 0; j < 4; j++)
#pragma unroll
            for (int q = 0; q < 4; q++) acc2[i][j][q] = 0.f;

    for (int k0 = 0; k0 < NH; k0 += 32) {
        const float4* wsrc = (const float4*)(W2 + ((size_t)e * NH + k0) * NH2);
#pragma unroll
        for (int i = 0; i < 2; i++) {
            int idx = tid + 512 * i;  // < 1024
            float4 f = wsrc[idx];
            int r = idx >> 5;         // 32 float4 per row
            int c = (idx & 31) * 4;
            uint32_t* d = (uint32_t*)&sW[r * LDW2 + c];
            d[0] = f2tf(f.x);
            d[1] = f2tf(f.y);
            d[2] = f2tf(f.z);
            d[3] = f2tf(f.w);
        }
        __syncthreads();
#pragma unroll
        for (int kk = 0; kk < 32; kk += 8) {
            uint32_t afr[2][4];
#pragma unroll
            for (int i = 0; i < 2; i++) {
                int r0 = wm2 * 32 + i * 16;
                afr[i][0] = sH1u[(r0 + g) * LDH + k0 + kk + t4];
                afr[i][1] = sH1u[(r0 + g + 8) * LDH + k0 + kk + t4];
                afr[i][2] = sH1u[(r0 + g) * LDH + k0 + kk + t4 + 4];
                afr[i][3] = sH1u[(r0 + g + 8) * LDH + k0 + kk + t4 + 4];
            }
#pragma unroll
            for (int j = 0; j < 4; j++) {
                uint32_t bfr[2];
                int c = wn2 * 32 + j * 8 + g;
                bfr[0] = sWu[(kk + t4) * LDW2 + c];
                bfr[1] = sWu[(kk + t4 + 4) * LDW2 + c];
                mma_tf32(acc2[0][j], afr[0], bfr);
                mma_tf32(acc2[1][j], afr[1], bfr);
            }
        }
        __syncthreads();
    }
    // all reads of sH1 are done; reuse region as sH2
#pragma unroll
    for (int i = 0; i < 2; i++) {
        int r0 = wm2 * 32 + i * 16 + g;
#pragma unroll
        for (int j = 0; j < 4; j++) {
            int c = wn2 * 32 + j * 8 + 2 * t4;
            *(float2*)&sH2[r0 * LDH2 + c] = make_float2(acc2[i][j][0], acc2[i][j][1]);
            *(float2*)&sH2[(r0 + 8) * LDH2 + c] = make_float2(acc2[i][j][2], acc2[i][j][3]);
        }
    }
    if (tid < NH2 * NO) sW3[tid] = W3[(size_t)e * NH2 * NO + tid];
    __syncthreads();
    // bias + ReLU on H2 (keep fp32 for the final FMA GEMM)
    for (int i = tid; i < 128 * NH2; i += 512) {
        int r = i >> 7, c = i & 127;
        float v = sH2[r * LDH2 + c] + b2[(size_t)e * NH2 + c];
        sH2[r * LDH2 + c] = fmaxf(v, 0.f);
    }
    __syncthreads();

    // ===================== GEMM3 + epilogue: [128,128] x [128,2] =====================
    if (tid < 256) {
        int r = tid >> 1, c = tid & 1;
        if (r < rows) {
            int gt = sTok[r];
            if (gt >= 0) {
                const float* hrow = &sH2[r * LDH2];
                float s = 0.f;
#pragma unroll 16
                for (int k = 0; k < NH2; k++) s += hrow[k] * sW3[k * 2 + c];
                float o = 0.7f * (s + b3[(size_t)e * NO + c]) + 0.3f * base[(size_t)gt * NO + c];
                out[(size_t)gt * NO + c] = o;
            }
        }
    }
}

// ---------------- launcher ----------------
extern "C" void kernel_launch(void* const* d_in, const int* in_sizes, int n_in,
                              void* d_out, int out_size) {
    const float* hidden = (const float*)d_in[0];
    const float* base = (const float*)d_in[1];
    const void* props = d_in[2];
    const float* mask = (const float*)d_in[3];
    const float* ln_g = (const float*)d_in[4];
    const float* ln_b = (const float*)d_in[5];
    const float* W1 = (const float*)d_in[6];
    const float* b1 = (const float*)d_in[7];
    const float* W2 = (const float*)d_in[8];
    const float* b2 = (const float*)d_in[9];
    const float* W3 = (const float*)d_in[10];
    const float* b3 = (const float*)d_in[11];
    float* out = (float*)d_out;

    cudaFuncSetAttribute(k_main, cudaFuncAttributeMaxDynamicSharedMemorySize, SMEM_BYTES);

    k_reset<<<1, 64>>>((const unsigned*)props);
    k_stats<<<N_TOK / 8, 256>>>(hidden, props, mask, out);
    k_plan<<<1, 32>>>();
    k_scatter<<<N_TOK / 256, 256>>>(props, mask);
    k_main<<<MAXT - 192, 512, SMEM_BYTES>>>(hidden, base, ln_g, ln_b,
                                            W1, b1, W2, b2, W3, b3, out);
}

// round 4
// speedup vs baseline: 1.3341x; 1.3341x over previous
#include <cuda_runtime.h>
#include <cstdint>

#define N_TOK 32768
#define DIM 768
#define NE 64
#define NH 256
#define NH2 128
#define NO 2

// ---------------- scratch (no allocations allowed) ----------------
__device__ float g_mu[N_TOK];
__device__ float g_rstd[N_TOK];
__device__ int g_hist[NE];
__device__ int g_off[NE + 1];
__device__ int g_cur[NE];
__device__ int g_tokidx[N_TOK];
__device__ int g_ntiles;
__device__ int g_p64;  // 1 if properties buffer is int64, 0 if int32
#define MAXT 320
__device__ int g_tile_head[MAXT];
__device__ int g_tile_start[MAXT];
__device__ int g_tile_rows[MAXT];

// ---------------- helpers ----------------
__device__ __forceinline__ void mma_tf32(float* d, const uint32_t* a, const uint32_t* b) {
    asm volatile(
        "mma.sync.aligned.m16n8k8.row.col.f32.tf32.tf32.f32 "
        "{%0,%1,%2,%3}, {%4,%5,%6,%7}, {%8,%9}, {%0,%1,%2,%3};\n"
        : "+f"(d[0]), "+f"(d[1]), "+f"(d[2]), "+f"(d[3])
        : "r"(a[0]), "r"(a[1]), "r"(a[2]), "r"(a[3]), "r"(b[0]), "r"(b[1]));
}

__device__ __forceinline__ void cp16(uint32_t dst_smem, const void* src) {
    asm volatile("cp.async.cg.shared.global [%0], [%1], 16;\n" ::"r"(dst_smem), "l"(src));
}
#define CP_COMMIT() asm volatile("cp.async.commit_group;\n" ::: "memory")
#define CP_WAIT0() asm volatile("cp.async.wait_group 0;\n" ::: "memory")

__device__ __forceinline__ int get_prop(const void* props, int t, int p64) {
    int v;
    if (p64) v = (int)((const long long*)props)[t];
    else     v = ((const int*)props)[t];
    return v & (NE - 1);
}

// ---------------- kernel 0: reset + dtype detection ----------------
__global__ void k_reset(const unsigned* __restrict__ pw) {
    if (threadIdx.x < NE) g_hist[threadIdx.x] = 0;
    // int64 with values in [0,64) => every odd 32-bit word zero.
    if (threadIdx.x < 32) {
        int odd_nonzero = 0;
#pragma unroll
        for (int i = 0; i < 4; i++)
            if (pw[2 * (threadIdx.x + 32 * i) + 1] != 0u) odd_nonzero = 1;
        unsigned b = __ballot_sync(0xFFFFFFFFu, odd_nonzero);
        if (threadIdx.x == 0) g_p64 = (b == 0u) ? 1 : 0;
    }
}

// ---------------- kernel 1: LN stats + histogram + masked-output zero ----------------
__global__ void k_stats(const float* __restrict__ hidden,
                        const void* __restrict__ props,
                        const float* __restrict__ mask,
                        float* __restrict__ out) {
    int token = blockIdx.x * 8 + (threadIdx.x >> 5);
    int lane = threadIdx.x & 31;
    const float4* xr = (const float4*)(hidden + (size_t)token * DIM);
    float s = 0.f, q = 0.f;
#pragma unroll
    for (int i = 0; i < DIM / 128; i++) {
        float4 v = xr[lane + 32 * i];
        s += v.x + v.y + v.z + v.w;
        q += v.x * v.x + v.y * v.y + v.z * v.z + v.w * v.w;
    }
#pragma unroll
    for (int o = 16; o > 0; o >>= 1) {
        s += __shfl_xor_sync(0xFFFFFFFFu, s, o);
        q += __shfl_xor_sync(0xFFFFFFFFu, q, o);
    }
    if (lane == 0) {
        float mu = s * (1.f / DIM);
        float var = q * (1.f / DIM) - mu * mu;
        g_mu[token] = mu;
        g_rstd[token] = rsqrtf(var + 1e-5f);
        float m = mask[token];
        if (m > 0.f) {
            atomicAdd(&g_hist[get_prop(props, token, g_p64)], 1);
        } else {
            out[token * 2 + 0] = 0.f;
            out[token * 2 + 1] = 0.f;
        }
    }
}

// ---------------- kernel 2: scan + tile plan (single block) ----------------
__global__ void k_plan() {
    if (threadIdx.x == 0) {
        int off = 0, nt = 0;
        for (int e = 0; e < NE; e++) {
            g_off[e] = off;
            int c = g_hist[e];
            for (int s = 0; s < c && nt < MAXT; s += 128) {
                g_tile_head[nt] = e;
                g_tile_start[nt] = off + s;
                g_tile_rows[nt] = min(128, c - s);
                nt++;
            }
            g_cur[e] = 0;
            off += c;
        }
        g_off[NE] = off;
        g_ntiles = nt;
    }
}

// ---------------- kernel 3: scatter (block-local ranks, 1 atomic/head/block) ----
__global__ void k_scatter(const void* __restrict__ props,
                          const float* __restrict__ mask) {
    __shared__ int h[NE], bs[NE];
    int tid = threadIdx.x;
    int t = blockIdx.x * 512 + tid;
    if (tid < NE) h[tid] = 0;
    __syncthreads();
    int p = -1, loc = 0;
    if (mask[t] > 0.f) {
        p = get_prop(props, t, g_p64);
        loc = atomicAdd(&h[p], 1);
    }
    __syncthreads();
    if (tid < NE && h[tid] > 0) bs[tid] = atomicAdd(&g_cur[tid], h[tid]);
    __syncthreads();
    if (p >= 0) {
        int dst = g_off[p] + bs[p] + loc;
        if (dst >= 0 && dst < N_TOK) g_tokidx[dst] = t;
    }
}

// ---------------- kernel 4: fused grouped adapter ----------------
#define LDA 36    // (36 % 32 == 4) -> conflict-free A-frag LDS
#define LDW 264   // (264 % 32 == 8) -> conflict-free B-frag LDS
#define LDW2 136  // (136 % 32 == 8)
#define LDH 260   // (260 % 32 == 4) -> conflict-free GEMM2 A-frag LDS
#define LDH2 132

// smem floats: A 128*36 + W 2*32*264 + H1 128*260 + GB 2*768 + TOK 128
#define SMEM_FLOATS (128 * LDA + 2 * 32 * LDW + 128 * LDH + 2 * DIM + 128)
#define SMEM_BYTES (SMEM_FLOATS * 4)

__global__ __launch_bounds__(512) void k_main(
    const float* __restrict__ hidden, const float* __restrict__ base,
    const float* __restrict__ ln_g, const float* __restrict__ ln_b,
    const float* __restrict__ W1, const float* __restrict__ b1,
    const float* __restrict__ W2, const float* __restrict__ b2,
    const float* __restrict__ W3, const float* __restrict__ b3,
    float* __restrict__ out)
{
    if ((int)blockIdx.x >= g_ntiles) return;

    extern __shared__ float sm[];
    float* sA = sm;                        // 4608
    float* sW = sA + 128 * LDA;            // 2 * 8448
    float* sH1 = sW + 2 * 32 * LDW;        // 33280
    float* sGB = sH1 + 128 * LDH;          // 1536 (gamma then beta)
    int* sTok = (int*)(sGB + 2 * DIM);     // 128
    float* sH2 = sH1;                      // reuses H1 region after GEMM2
    float* sW3 = sA;                       // 256 floats, reuses A after GEMM1

    const int tid = threadIdx.x;
    const int wid = tid >> 5;
    const int lane = tid & 31;
    const int g = lane >> 2;
    const int t4 = lane & 3;
    const int e = g_tile_head[blockIdx.x] & (NE - 1);
    const int seg = g_tile_start[blockIdx.x];
    const int rows = g_tile_rows[blockIdx.x];

    if (tid < 128) {
        int tok = -1;
        if (tid < rows) {
            tok = g_tokidx[seg + tid];
            if (tok < 0 || tok >= N_TOK) tok = -1;
        }
        sTok[tid] = tok;
    }
    // gamma/beta to smem once (768 + 768 floats)
    {
        const float4* gp = (const float4*)(ln_g + (size_t)e * DIM);
        const float4* bp = (const float4*)(ln_b + (size_t)e * DIM);
        if (tid < DIM / 4) {
            ((float4*)sGB)[tid] = gp[tid];
            ((float4*)(sGB + DIM))[tid] = bp[tid];
        }
    }
    __syncthreads();

    const int arow = tid >> 2;
    const int acol = (tid & 3) * 8;
    const int tokr = sTok[arow];
    float mu = 0.f, rs = 0.f;
    const float* xrow = hidden;
    if (tokr >= 0) {
        mu = g_mu[tokr];
        rs = g_rstd[tokr];
        xrow = hidden + (size_t)tokr * DIM;
    }

    const uint32_t* sAu = (const uint32_t*)sA;
    const uint32_t* sH1u = (const uint32_t*)sH1;
    const uint32_t swbase = (uint32_t)__cvta_generic_to_shared(sW);

    // ===================== GEMM1: [128,768] x [768,256] =====================
    const int wm = wid >> 2;
    const int wn = wid & 3;
    float acc1[2][8][4];
#pragma unroll
    for (int i = 0; i < 2; i++)
#pragma unroll
        for (int j = 0; j < 8; j++)
#pragma unroll
            for (int q = 0; q < 4; q++) acc1[i][j][q] = 0.f;

    // cp.async of W1 chunk [32,256] into wbuf (2048 x 16B, 4 per thread)
    const int wr = tid >> 6;          // base row (x4 rows via +8 stride pattern below)
    // per thread: idx = tid + 512*i ; r = idx>>6 ; c=(idx&63)*4
#define CP_W1(k0, buf)                                                             \
    {                                                                              \
        const float* src0 = W1 + ((size_t)e * DIM + (k0)) * NH;                    \
        _Pragma("unroll") for (int i = 0; i < 4; i++) {                            \
            int idx = tid + 512 * i;                                               \
            int r = idx >> 6, c = (idx & 63) * 4;                                  \
            cp16(swbase + (uint32_t)(((buf)*32 * LDW + r * LDW + c) * 4),          \
                 src0 + r * NH + c);                                               \
        }                                                                          \
        CP_COMMIT();                                                               \
    }

    float4 x0, x1, g0, g1, c0, c1;
    // prologue: W chunk 0 + x regs chunk 0
    CP_W1(0, 0);
    if (tokr >= 0) {
        x0 = *(const float4*)(xrow + acol);
        x1 = *(const float4*)(xrow + acol + 4);
    }
    g0 = *(const float4*)(sGB + acol);
    g1 = *(const float4*)(sGB + acol + 4);
    c0 = *(const float4*)(sGB + DIM + acol);
    c1 = *(const float4*)(sGB + DIM + acol + 4);

    for (int i = 0; i < DIM / 32; i++) {
        const int cur = i & 1;
        const int k0 = i * 32;
        CP_WAIT0();
        __syncthreads();  // W(i) visible everywhere; previous MMA done
        if (i < DIM / 32 - 1) CP_W1(k0 + 32, cur ^ 1);
        // transform + store A(i)
        {
            float* d = &sA[arow * LDA + acol];
            if (tokr >= 0) {
                float4 o0, o1;
                o0.x = (x0.x - mu) * rs * g0.x + c0.x;
                o0.y = (x0.y - mu) * rs * g0.y + c0.y;
                o0.z = (x0.z - mu) * rs * g0.z + c0.z;
                o0.w = (x0.w - mu) * rs * g0.w + c0.w;
                o1.x = (x1.x - mu) * rs * g1.x + c1.x;
                o1.y = (x1.y - mu) * rs * g1.y + c1.y;
                o1.z = (x1.z - mu) * rs * g1.z + c1.z;
                o1.w = (x1.w - mu) * rs * g1.w + c1.w;
                *(float4*)d = o0;
                *(float4*)(d + 4) = o1;
            } else {
                *(float4*)d = make_float4(0.f, 0.f, 0.f, 0.f);
                *(float4*)(d + 4) = make_float4(0.f, 0.f, 0.f, 0.f);
            }
        }
        // prefetch x + gamma/beta for chunk i+1 (overlaps MMA below)
        if (i < DIM / 32 - 1) {
            int kn = k0 + 32;
            if (tokr >= 0) {
                x0 = *(const float4*)(xrow + kn + acol);
                x1 = *(const float4*)(xrow + kn + acol + 4);
            }
            g0 = *(const float4*)(sGB + kn + acol);
            g1 = *(const float4*)(sGB + kn + acol + 4);
            c0 = *(const float4*)(sGB + DIM + kn + acol);
            c1 = *(const float4*)(sGB + DIM + kn + acol + 4);
        }
        __syncthreads();  // A(i) visible
        const uint32_t* wb = (const uint32_t*)(sW + cur * 32 * LDW);
#pragma unroll
        for (int kk = 0; kk < 32; kk += 8) {
            uint32_t afr[2][4];
#pragma unroll
            for (int m = 0; m < 2; m++) {
                int r0 = wm * 32 + m * 16;
                afr[m][0] = sAu[(r0 + g) * LDA + kk + t4];
                afr[m][1] = sAu[(r0 + g + 8) * LDA + kk + t4];
                afr[m][2] = sAu[(r0 + g) * LDA + kk + t4 + 4];
                afr[m][3] = sAu[(r0 + g + 8) * LDA + kk + t4 + 4];
            }
#pragma unroll
            for (int j = 0; j < 8; j++) {
                uint32_t bfr[2];
                int c = wn * 64 + j * 8 + g;
                bfr[0] = wb[(kk + t4) * LDW + c];
                bfr[1] = wb[(kk + t4 + 4) * LDW + c];
                mma_tf32(acc1[0][j], afr[0], bfr);
                mma_tf32(acc1[1][j], afr[1], bfr);
            }
        }
    }
    __syncthreads();
    // store acc1 -> sH1
#pragma unroll
    for (int m = 0; m < 2; m++) {
        int r0 = wm * 32 + m * 16 + g;
#pragma unroll
        for (int j = 0; j < 8; j++) {
            int c = wn * 64 + j * 8 + 2 * t4;
            *(float2*)&sH1[r0 * LDH + c] = make_float2(acc1[m][j][0], acc1[m][j][1]);
            *(float2*)&sH1[(r0 + 8) * LDH + c] = make_float2(acc1[m][j][2], acc1[m][j][3]);
        }
    }
    __syncthreads();
    // bias + ReLU on H1 (raw fp32; tf32 MMA truncates)
    for (int i = tid; i < 128 * NH; i += 512) {
        int r = i >> 8, c = i & 255;
        float v = sH1[r * LDH + c] + b1[(size_t)e * NH + c];
        sH1[r * LDH + c] = fmaxf(v, 0.f);
    }

    // ===================== GEMM2: [128,256] x [256,128] =====================
    const int wm2 = wid >> 2;
    const int wn2 = wid & 3;
    float acc2[2][4][4];
#pragma unroll
    for (int i = 0; i < 2; i++)
#pragma unroll
        for (int j = 0; j < 4; j++)
#pragma unroll
            for (int q = 0; q < 4; q++) acc2[i][j][q] = 0.f;

#define CP_W2(k0, buf)                                                              \
    {                                                                               \
        const float* src0 = W2 + ((size_t)e * NH + (k0)) * NH2;                     \
        _Pragma("unroll") for (int i = 0; i < 2; i++) {                             \
            int idx = tid + 512 * i;                                                \
            int r = idx >> 5, c = (idx & 31) * 4;                                   \
            cp16(swbase + (uint32_t)(((buf)*32 * LDW2 + r * LDW2 + c) * 4),         \
                 src0 + r * NH2 + c);                                               \
        }                                                                           \
        CP_COMMIT();                                                                \
    }

    CP_W2(0, 0);  // prologue (issued before H1 sync is fine: W buffers idle)
    for (int i = 0; i < NH / 32; i++) {
        const int cur = i & 1;
        const int k0 = i * 32;
        CP_WAIT0();
        __syncthreads();  // W2(i) visible; H1 pass done (i==0); prev MMA done
        if (i < NH / 32 - 1) CP_W2(k0 + 32, cur ^ 1);
        const uint32_t* wb = (const uint32_t*)(sW + cur * 32 * LDW2);
#pragma unroll
        for (int kk = 0; kk < 32; kk += 8) {
            uint32_t afr[2][4];
#pragma unroll
            for (int m = 0; m < 2; m++) {
                int r0 = wm2 * 32 + m * 16;
                afr[m][0] = sH1u[(r0 + g) * LDH + k0 + kk + t4];
                afr[m][1] = sH1u[(r0 + g + 8) * LDH + k0 + kk + t4];
                afr[m][2] = sH1u[(r0 + g) * LDH + k0 + kk + t4 + 4];
                afr[m][3] = sH1u[(r0 + g + 8) * LDH + k0 + kk + t4 + 4];
            }
#pragma unroll
            for (int j = 0; j < 4; j++) {
                uint32_t bfr[2];
                int c = wn2 * 32 + j * 8 + g;
                bfr[0] = wb[(kk + t4) * LDW2 + c];
                bfr[1] = wb[(kk + t4 + 4) * LDW2 + c];
                mma_tf32(acc2[0][j], afr[0], bfr);
                mma_tf32(acc2[1][j], afr[1], bfr);
            }
        }
    }
    __syncthreads();  // all H1 reads done; reuse region as sH2
#pragma unroll
    for (int m = 0; m < 2; m++) {
        int r0 = wm2 * 32 + m * 16 + g;
#pragma unroll
        for (int j = 0; j < 4; j++) {
            int c = wn2 * 32 + j * 8 + 2 * t4;
            *(float2*)&sH2[r0 * LDH2 + c] = make_float2(acc2[m][j][0], acc2[m][j][1]);
            *(float2*)&sH2[(r0 + 8) * LDH2 + c] = make_float2(acc2[m][j][2], acc2[m][j][3]);
        }
    }
    if (tid < NH2 * NO) sW3[tid] = W3[(size_t)e * NH2 * NO + tid];
    __syncthreads();
    for (int i = tid; i < 128 * NH2; i += 512) {
        int r = i >> 7, c = i & 127;
        float v = sH2[r * LDH2 + c] + b2[(size_t)e * NH2 + c];
        sH2[r * LDH2 + c] = fmaxf(v, 0.f);
    }
    __syncthreads();

    // ===================== GEMM3 + epilogue =====================
    if (tid < 256) {
        int r = tid >> 1, c = tid & 1;
        if (r < rows) {
            int gt = sTok[r];
            if (gt >= 0) {
                const float* hrow = &sH2[r * LDH2];
                float s = 0.f;
#pragma unroll 16
                for (int k = 0; k < NH2; k++) s += hrow[k] * sW3[k * 2 + c];
                float o = 0.7f * (s + b3[(size_t)e * NO + c]) + 0.3f * base[(size_t)gt * NO + c];
                out[(size_t)gt * NO + c] = o;
            }
        }
    }
    (void)wr;
}

// ---------------- launcher ----------------
extern "C" void kernel_launch(void* const* d_in, const int* in_sizes, int n_in,
                              void* d_out, int out_size) {
    const float* hidden = (const float*)d_in[0];
    const float* base = (const float*)d_in[1];
    const void* props = d_in[2];
    const float* mask = (const float*)d_in[3];
    const float* ln_g = (const float*)d_in[4];
    const float* ln_b = (const float*)d_in[5];
    const float* W1 = (const float*)d_in[6];
    const float* b1 = (const float*)d_in[7];
    const float* W2 = (const float*)d_in[8];
    const float* b2 = (const float*)d_in[9];
    const float* W3 = (const float*)d_in[10];
    const float* b3 = (const float*)d_in[11];
    float* out = (float*)d_out;

    cudaFuncSetAttribute(k_main, cudaFuncAttributeMaxDynamicSharedMemorySize, SMEM_BYTES);

    k_reset<<<1, 64>>>((const unsigned*)props);
    k_stats<<<N_TOK / 8, 256>>>(hidden, props, mask, out);
    k_plan<<<1, 32>>>();
    k_scatter<<<N_TOK / 512, 512>>>(props, mask);
    k_main<<<MAXT, 512, SMEM_BYTES>>>(hidden, base, ln_g, ln_b,
                                      W1, b1, W2, b2, W3, b3, out);
}